// round 13
// baseline (speedup 1.0000x reference)
#include <cuda_runtime.h>
#include <cuda_bf16.h>
#include <cstdint>

#define Bb 32
#define Dd 2048
#define Tt 512
#define Kk 512
#define Nn (Bb*Tt)            // 16384
#define BDT (Bb*Dd*Tt)        // 33554432
#define OH1_OFF BDT
#define BAR_OFF (BDT + Nn)
#define OH2_OFF (2*BDT + Nn)
#define MARGIN 2e-3f

// ---------------- scratch (device globals; allocation-free) ----------------
__device__ __nv_bfloat16 g_a0[(size_t)Nn * Dd];   // z bf16, n-major
__device__ float         g_at[(size_t)Nn * Dd];   // z fp32, n-major (exact)
__device__ __nv_bfloat16 g_b0[(size_t)Kk * Dd];   // codebook bf16
__device__ float g_dots[(size_t)Nn * Kk];         // approx scores (32 MB)
__device__ float g_S[Nn];
__device__ float g_C2[Kk];
__device__ int   g_idx[Nn];

__device__ __forceinline__ uint32_t smem_u32(const void* p) {
    uint32_t a;
    asm("{ .reg .u64 t; cvta.to.shared.u64 t, %1; cvt.u32.u64 %0, t; }" : "=r"(a) : "l"(p));
    return a;
}
__device__ __forceinline__ uint32_t sw_off(int r, int cbyte) {
    return (uint32_t)(r * 128 + (cbyte ^ ((r & 7) << 4)));
}

#define LDSM4(f, addr) \
    asm volatile("ldmatrix.sync.aligned.m8n8.x4.shared.b16 {%0,%1,%2,%3}, [%4];" \
        : "=r"((f)[0]), "=r"((f)[1]), "=r"((f)[2]), "=r"((f)[3]) : "r"(addr))

#define MMA16816(d, a, br0, br1) \
    asm volatile("mma.sync.aligned.m16n8k16.row.col.f32.bf16.bf16.f32 " \
        "{%0,%1,%2,%3}, {%4,%5,%6,%7}, {%8,%9}, {%0,%1,%2,%3};" \
        : "+f"((d)[0]), "+f"((d)[1]), "+f"((d)[2]), "+f"((d)[3]) \
        : "r"((a)[0]), "r"((a)[1]), "r"((a)[2]), "r"((a)[3]), "r"(br0), "r"(br1))

// ---------------------------------------------------------------------------
// fused prep: blocks [0,512) = codebook C2 + bf16 copy (validated body);
//             blocks [512,1024) = z transpose/split + S (validated body)
// ---------------------------------------------------------------------------
__global__ void __launch_bounds__(256) k_prep(const float* __restrict__ z,
                                              const float* __restrict__ cb) {
    __shared__ float s[64][33];
    __shared__ float red[32][9];
    __shared__ float smr[256];

    if (blockIdx.x < 512) {
        int k = blockIdx.x;
        const float4* row = (const float4*)(cb + (size_t)k * Dd);
        float sv = 0.f;
        for (int i = threadIdx.x; i < Dd / 4; i += 256) {
            float4 v = row[i];
            sv += v.x * v.x + v.y * v.y + v.z * v.z + v.w * v.w;
            __nv_bfloat16 h[4];
            h[0] = __float2bfloat16(v.x); h[1] = __float2bfloat16(v.y);
            h[2] = __float2bfloat16(v.z); h[3] = __float2bfloat16(v.w);
            *(uint2*)&g_b0[(size_t)k * Dd + 4 * i] = *(uint2*)h;
        }
        smr[threadIdx.x] = sv;
        __syncthreads();
        for (int o = 128; o; o >>= 1) {
            if (threadIdx.x < o) smr[threadIdx.x] += smr[threadIdx.x + o];
            __syncthreads();
        }
        if (threadIdx.x == 0) g_C2[k] = smr[0];
        return;
    }

    int idx = blockIdx.x - 512;
    int t0 = (idx & 15) * 32;
    int b  = idx >> 4;
    const float* zp = z + (size_t)b * Dd * Tt + t0;

    int nl = threadIdx.x >> 3;
    int dc = (threadIdx.x & 7) * 8;
    size_t nrow = (size_t)(b * Tt + t0 + nl) * Dd;
    float Sacc = 0.f;

    for (int dt = 0; dt < 32; dt++) {
        int d0 = dt * 64;
#pragma unroll
        for (int i = 0; i < 8; i++) {
            int e = i * 256 + threadIdx.x;
            int dr = e >> 5, tc = e & 31;
            s[dr][tc] = zp[(size_t)(d0 + dr) * Tt + tc];
        }
        __syncthreads();

        float f[8];
        __nv_bfloat16 h[8];
#pragma unroll
        for (int j = 0; j < 8; j++) {
            f[j] = s[dc + j][nl];
            h[j] = __float2bfloat16(f[j]);
            Sacc += f[j] * f[j];
        }
        *(float4*)&g_at[nrow + d0 + dc]     = *(float4*)(f + 0);
        *(float4*)&g_at[nrow + d0 + dc + 4] = *(float4*)(f + 4);
        *(uint4*)&g_a0[nrow + d0 + dc]      = *(uint4*)h;
        __syncthreads();
    }

    red[nl][threadIdx.x & 7] = Sacc;
    __syncthreads();
    if (threadIdx.x < 32) {
        float t = 0.f;
#pragma unroll
        for (int g = 0; g < 8; g++) t += red[threadIdx.x][g];
        g_S[b * Tt + t0 + threadIdx.x] = t;
    }
}

// ---------------------------------------------------------------------------
// single-pass bf16 mma.sync GEMM -> g_dots  (exact R11 kernel, validated)
// ---------------------------------------------------------------------------
#define TILE_BYTES 16384
#define STAGE_BYTES (2*TILE_BYTES)
#define SM_SZ (3*STAGE_BYTES)      // 98304

__global__ void __launch_bounds__(256) k_gemm_mma() {
    extern __shared__ char sm[];
    const int tid  = threadIdx.x;
    const int lane = tid & 31, wid = tid >> 5;
    const int mw = wid & 1, nw = wid >> 1;
    const int n0 = blockIdx.y * 128;
    const int k0 = blockIdx.x * 128;

    const __nv_bfloat16* srcs[2];
    srcs[0] = g_a0 + (size_t)n0 * Dd;
    srcs[1] = g_b0 + (size_t)k0 * Dd;

    const uint32_t smbase = smem_u32(sm);

    auto stage_load = [&](int kt, int slot) {
        const int d0 = kt * 64;
        const uint32_t sbase = smbase + slot * STAGE_BYTES;
#pragma unroll
        for (int i = 0; i < 8; i++) {
            int q = i * 256 + tid;
            int tile = q >> 10;
            int qq = q & 1023;
            int r = qq >> 3, c16 = (qq & 7) << 4;
            uint32_t dst = sbase + tile * TILE_BYTES + sw_off(r, c16);
            const void* src = (const char*)(srcs[tile] + (size_t)r * Dd + d0) + c16;
            asm volatile("cp.async.cg.shared.global [%0], [%1], 16;" :: "r"(dst), "l"(src));
        }
        asm volatile("cp.async.commit_group;" ::: "memory");
    };

    float acc[4][4][4];
#pragma unroll
    for (int a = 0; a < 4; a++)
#pragma unroll
        for (int b = 0; b < 4; b++)
#pragma unroll
            for (int c = 0; c < 4; c++) acc[a][b][c] = 0.f;

    stage_load(0, 0);
    stage_load(1, 1);

    for (int kt = 0; kt < 32; kt++) {
        asm volatile("cp.async.wait_group 1;" ::: "memory");
        __syncthreads();
        if (kt + 2 < 32) stage_load(kt + 2, (kt + 2) % 3);

        const uint32_t sb  = smbase + (kt % 3) * STAGE_BYTES;
        const uint32_t a0b = sb;
        const uint32_t b0b = sb + TILE_BYTES;

#pragma unroll
        for (int kk = 0; kk < 4; kk++) {
            const int cba = kk * 32 + ((lane >> 4) & 1) * 16;
            const int cbb = kk * 32 + ((lane >> 3) & 1) * 16;
            uint32_t a0f[4][4];
#pragma unroll
            for (int mi = 0; mi < 4; mi++) {
                int r = mw * 64 + mi * 16 + (lane & 15);
                LDSM4(a0f[mi], a0b + sw_off(r, cba));
            }
            uint32_t b0f[2][4];
#pragma unroll
            for (int nj = 0; nj < 2; nj++) {
                int r = nw * 32 + nj * 16 + (lane & 7) + ((lane >> 4) & 1) * 8;
                LDSM4(b0f[nj], b0b + sw_off(r, cbb));
            }
#pragma unroll
            for (int mi = 0; mi < 4; mi++)
#pragma unroll
                for (int ni = 0; ni < 4; ni++) {
                    const uint32_t* p0 = &b0f[ni >> 1][(ni & 1) * 2];
                    MMA16816(acc[mi][ni], a0f[mi], p0[0], p0[1]);
                }
        }
    }

#pragma unroll
    for (int mi = 0; mi < 4; mi++) {
        int rbase = n0 + mw * 64 + mi * 16 + (lane >> 2);
#pragma unroll
        for (int ni = 0; ni < 4; ni++) {
            int c = k0 + nw * 32 + ni * 8 + (lane & 3) * 2;
            *(float2*)&g_dots[(size_t)rbase * Kk + c]       = make_float2(acc[mi][ni][0], acc[mi][ni][1]);
            *(float2*)&g_dots[(size_t)(rbase + 8) * Kk + c] = make_float2(acc[mi][ni][2], acc[mi][ni][3]);
        }
    }
}

// ---------------------------------------------------------------------------
// fused select: approx argmin + margin shortlist; cnt==1 fast path (validated)
// ---------------------------------------------------------------------------
__global__ void __launch_bounds__(256) k_select(const float* __restrict__ cb) {
    int w = threadIdx.x >> 5, lane = threadIdx.x & 31;
    int n = blockIdx.x * 8 + w;
    float S = g_S[n];
    const float* row = g_dots + (size_t)n * Kk;

    float v[16];
    float best = 3.4e38f;
#pragma unroll
    for (int i = 0; i < 16; i++) {
        int k = i * 32 + lane;
        float m  = __fmul_rn(2.0f, row[k]);
        float v1 = __fadd_rn(S, -m);
        v[i] = __fadd_rn(v1, g_C2[k]);
        best = fminf(best, v[i]);
    }
#pragma unroll
    for (int off = 16; off; off >>= 1)
        best = fminf(best, __shfl_xor_sync(0xFFFFFFFFu, best, off));
    float thr = best + MARGIN;

    unsigned masks[16];
    int total = 0;
#pragma unroll
    for (int i = 0; i < 16; i++) {
        masks[i] = __ballot_sync(0xFFFFFFFFu, v[i] <= thr);
        total += __popc(masks[i]);
    }

    if (total == 1) {
        if (lane == 0) {
            int kk = 0;
#pragma unroll
            for (int i = 0; i < 16; i++)
                if (masks[i]) kk = i * 32 + (__ffs(masks[i]) - 1);
            g_idx[n] = kk;
        }
        return;
    }

    const float* arow = g_at + (size_t)n * Dd;
    unsigned long long bkey = 0xFFFFFFFFFFFFFFFFull;
#pragma unroll
    for (int i = 0; i < 16; i++) {
        unsigned mask = masks[i];
        while (mask) {
            int src = __ffs(mask) - 1;
            mask &= mask - 1;
            int k = i * 32 + src;
            const float* brow = cb + (size_t)k * Dd;
            float acc = 0.f;
#pragma unroll
            for (int j = 0; j < 16; j++) {
                float4 a = *(const float4*)(arow + j * 128 + lane * 4);
                float4 b = *(const float4*)(brow + j * 128 + lane * 4);
                acc = fmaf(a.x, b.x, acc);
                acc = fmaf(a.y, b.y, acc);
                acc = fmaf(a.z, b.z, acc);
                acc = fmaf(a.w, b.w, acc);
            }
#pragma unroll
            for (int off = 16; off; off >>= 1)
                acc += __shfl_xor_sync(0xFFFFFFFFu, acc, off);
            float vv = __fadd_rn(__fadd_rn(S, -__fmul_rn(2.0f, acc)), g_C2[k]);
            unsigned long long kk =
                ((unsigned long long)__float_as_uint(vv) << 32) | (unsigned)k;
            if (kk < bkey) bkey = kk;
        }
    }
    if (lane == 0) g_idx[n] = (int)(bkey & 0xFFFFFFFFull);
}

// ---------------------------------------------------------------------------
// scatter + conv: block = 64 t (float2 per lane), double-buffered 64-d staging
// same add order as validated R11 scatter -> bit-identical outputs
// ---------------------------------------------------------------------------
__global__ void __launch_bounds__(256) k_scatter3(const float* __restrict__ z,
                                                  const float* __restrict__ cb,
                                                  const float* __restrict__ cw,
                                                  const float* __restrict__ cbias,
                                                  float* __restrict__ out) {
    __shared__ int   sidx[64];
    __shared__ float scb[2][64][65];
    __shared__ float r1x[8][33], r1y[8][33], r2x[8][33], r2y[8][33];

    int b  = blockIdx.y;
    int t0 = blockIdx.x * 64;
    int w = threadIdx.x >> 5, lane = threadIdx.x & 31;

    if (threadIdx.x < 64)
        sidx[threadIdx.x] = g_idx[b * Tt + t0 + threadIdx.x];
    __syncthreads();

    // prefetch tile 0: 64 rows x 64 floats
#pragma unroll
    for (int i = 0; i < 4; i++) {
        int q = i * 256 + threadIdx.x;
        int row = q >> 4, c4 = (q & 15) << 2;
        float4 v = *(const float4*)(cb + (size_t)sidx[row] * Dd + c4);
        scb[0][row][c4 + 0] = v.x;
        scb[0][row][c4 + 1] = v.y;
        scb[0][row][c4 + 2] = v.z;
        scb[0][row][c4 + 3] = v.w;
    }
    __syncthreads();

    float a1x = 0.f, a1y = 0.f, a2x = 0.f, a2y = 0.f;
    for (int dt = 0; dt < 32; dt++) {
        int d0 = dt * 64;
        int cur = dt & 1;
        if (dt + 1 < 32) {
            int d1 = d0 + 64;
#pragma unroll
            for (int i = 0; i < 4; i++) {
                int q = i * 256 + threadIdx.x;
                int row = q >> 4, c4 = (q & 15) << 2;
                float4 v = *(const float4*)(cb + (size_t)sidx[row] * Dd + d1 + c4);
                scb[cur ^ 1][row][c4 + 0] = v.x;
                scb[cur ^ 1][row][c4 + 1] = v.y;
                scb[cur ^ 1][row][c4 + 2] = v.z;
                scb[cur ^ 1][row][c4 + 3] = v.w;
            }
        }

        const float* zp = z   + (size_t)b * Dd * Tt + (size_t)d0 * Tt + t0 + lane * 2;
        float*       o1 = out + (size_t)b * Dd * Tt + (size_t)d0 * Tt + t0 + lane * 2;
        float*       o3 = o1 + BAR_OFF;
#pragma unroll
        for (int j = 0; j < 8; j++) {
            int dl = w * 8 + j;
            float q0 = scb[cur][lane * 2][dl];
            float q1 = scb[cur][lane * 2 + 1][dl];
            float2 zv = *(const float2*)&zp[(size_t)dl * Tt];
            float zq0 = __fadd_rn(zv.x, __fadd_rn(q0, -zv.x));
            float zq1 = __fadd_rn(zv.y, __fadd_rn(q1, -zv.y));
            *(float2*)&o1[(size_t)dl * Tt] = make_float2(zq0, zq1);
            *(float2*)&o3[(size_t)dl * Tt] = make_float2(q0, q1);
            float wv = __ldg(cw + d0 + dl);
            a1x += zq0 * wv; a1y += zq1 * wv;
            a2x += q0 * wv;  a2y += q1 * wv;
        }
        __syncthreads();
    }

    r1x[w][lane] = a1x; r1y[w][lane] = a1y;
    r2x[w][lane] = a2x; r2y[w][lane] = a2y;
    __syncthreads();
    if (w == 0) {
        float bias = __ldg(cbias);
        float s1x = 0.f, s1y = 0.f, s2x = 0.f, s2y = 0.f;
#pragma unroll
        for (int i = 0; i < 8; i++) {
            s1x += r1x[i][lane]; s1y += r1y[i][lane];
            s2x += r2x[i][lane]; s2y += r2y[i][lane];
        }
        out[OH1_OFF + b * Tt + t0 + lane * 2]     = bias + s1x;
        out[OH1_OFF + b * Tt + t0 + lane * 2 + 1] = bias + s1y;
        out[OH2_OFF + b * Tt + t0 + lane * 2]     = bias + s2x;
        out[OH2_OFF + b * Tt + t0 + lane * 2 + 1] = bias + s2y;
    }
}

// ---------------------------------------------------------------------------
extern "C" void kernel_launch(void* const* d_in, const int* in_sizes, int n_in,
                              void* d_out, int out_size) {
    const float* z      = (const float*)d_in[0];
    const float* cb     = (const float*)d_in[1];
    const float* conv_w = (const float*)d_in[2];
    const float* conv_b = (const float*)d_in[3];
    float* out = (float*)d_out;

    cudaFuncSetAttribute(k_gemm_mma, cudaFuncAttributeMaxDynamicSharedMemorySize, SM_SZ);

    k_prep<<<1024, 256>>>(z, cb);
    k_gemm_mma<<<dim3(Kk / 128, Nn / 128), 256, SM_SZ>>>();
    k_select<<<Nn / 8, 256>>>(cb);
    k_scatter3<<<dim3(Tt / 64, Bb), 256>>>(z, cb, conv_w, conv_b, out);
}

// round 14
// speedup vs baseline: 1.1056x; 1.1056x over previous
#include <cuda_runtime.h>
#include <cuda_bf16.h>
#include <cstdint>

#define Bb 32
#define Dd 2048
#define Tt 512
#define Kk 512
#define Nn (Bb*Tt)            // 16384
#define BDT (Bb*Dd*Tt)        // 33554432
#define OH1_OFF BDT
#define BAR_OFF (BDT + Nn)
#define OH2_OFF (2*BDT + Nn)
#define MARGIN 2e-3f

// ---------------- scratch (device globals; allocation-free) ----------------
__device__ __nv_bfloat16 g_a0[(size_t)Nn * Dd];   // z bf16, n-major
__device__ float         g_at[(size_t)Nn * Dd];   // z fp32, n-major (exact)
__device__ __nv_bfloat16 g_b0[(size_t)Kk * Dd];   // codebook bf16
__device__ float g_dots[(size_t)Nn * Kk];         // approx scores (32 MB)
__device__ float g_S[Nn];
__device__ float g_C2[Kk];
__device__ int   g_idx[Nn];
__device__ float g_p1[(size_t)Nn * 4];            // conv partials (z_q_x path)
__device__ float g_p2[(size_t)Nn * 4];            // conv partials (quant path)

__device__ __forceinline__ uint32_t smem_u32(const void* p) {
    uint32_t a;
    asm("{ .reg .u64 t; cvta.to.shared.u64 t, %1; cvt.u32.u64 %0, t; }" : "=r"(a) : "l"(p));
    return a;
}
__device__ __forceinline__ uint32_t sw_off(int r, int cbyte) {
    return (uint32_t)(r * 128 + (cbyte ^ ((r & 7) << 4)));
}

#define LDSM4(f, addr) \
    asm volatile("ldmatrix.sync.aligned.m8n8.x4.shared.b16 {%0,%1,%2,%3}, [%4];" \
        : "=r"((f)[0]), "=r"((f)[1]), "=r"((f)[2]), "=r"((f)[3]) : "r"(addr))

#define MMA16816(d, a, br0, br1) \
    asm volatile("mma.sync.aligned.m16n8k16.row.col.f32.bf16.bf16.f32 " \
        "{%0,%1,%2,%3}, {%4,%5,%6,%7}, {%8,%9}, {%0,%1,%2,%3};" \
        : "+f"((d)[0]), "+f"((d)[1]), "+f"((d)[2]), "+f"((d)[3]) \
        : "r"((a)[0]), "r"((a)[1]), "r"((a)[2]), "r"((a)[3]), "r"(br0), "r"(br1))

// ---------------------------------------------------------------------------
// fused prep: blocks [0,512) = codebook C2 + bf16 copy;
//             blocks [512,1024) = z transpose/split + S  (validated R13)
// ---------------------------------------------------------------------------
__global__ void __launch_bounds__(256) k_prep(const float* __restrict__ z,
                                              const float* __restrict__ cb) {
    __shared__ float s[64][33];
    __shared__ float red[32][9];
    __shared__ float smr[256];

    if (blockIdx.x < 512) {
        int k = blockIdx.x;
        const float4* row = (const float4*)(cb + (size_t)k * Dd);
        float sv = 0.f;
        for (int i = threadIdx.x; i < Dd / 4; i += 256) {
            float4 v = row[i];
            sv += v.x * v.x + v.y * v.y + v.z * v.z + v.w * v.w;
            __nv_bfloat16 h[4];
            h[0] = __float2bfloat16(v.x); h[1] = __float2bfloat16(v.y);
            h[2] = __float2bfloat16(v.z); h[3] = __float2bfloat16(v.w);
            *(uint2*)&g_b0[(size_t)k * Dd + 4 * i] = *(uint2*)h;
        }
        smr[threadIdx.x] = sv;
        __syncthreads();
        for (int o = 128; o; o >>= 1) {
            if (threadIdx.x < o) smr[threadIdx.x] += smr[threadIdx.x + o];
            __syncthreads();
        }
        if (threadIdx.x == 0) g_C2[k] = smr[0];
        return;
    }

    int idx = blockIdx.x - 512;
    int t0 = (idx & 15) * 32;
    int b  = idx >> 4;
    const float* zp = z + (size_t)b * Dd * Tt + t0;

    int nl = threadIdx.x >> 3;
    int dc = (threadIdx.x & 7) * 8;
    size_t nrow = (size_t)(b * Tt + t0 + nl) * Dd;
    float Sacc = 0.f;

    for (int dt = 0; dt < 32; dt++) {
        int d0 = dt * 64;
#pragma unroll
        for (int i = 0; i < 8; i++) {
            int e = i * 256 + threadIdx.x;
            int dr = e >> 5, tc = e & 31;
            s[dr][tc] = zp[(size_t)(d0 + dr) * Tt + tc];
        }
        __syncthreads();

        float f[8];
        __nv_bfloat16 h[8];
#pragma unroll
        for (int j = 0; j < 8; j++) {
            f[j] = s[dc + j][nl];
            h[j] = __float2bfloat16(f[j]);
            Sacc += f[j] * f[j];
        }
        *(float4*)&g_at[nrow + d0 + dc]     = *(float4*)(f + 0);
        *(float4*)&g_at[nrow + d0 + dc + 4] = *(float4*)(f + 4);
        *(uint4*)&g_a0[nrow + d0 + dc]      = *(uint4*)h;
        __syncthreads();
    }

    red[nl][threadIdx.x & 7] = Sacc;
    __syncthreads();
    if (threadIdx.x < 32) {
        float t = 0.f;
#pragma unroll
        for (int g = 0; g < 8; g++) t += red[threadIdx.x][g];
        g_S[b * Tt + t0 + threadIdx.x] = t;
    }
}

// ---------------------------------------------------------------------------
// single-pass bf16 mma.sync GEMM -> g_dots  (exact R11 kernel, validated)
// ---------------------------------------------------------------------------
#define TILE_BYTES 16384
#define STAGE_BYTES (2*TILE_BYTES)
#define SM_SZ (3*STAGE_BYTES)      // 98304

__global__ void __launch_bounds__(256) k_gemm_mma() {
    extern __shared__ char sm[];
    const int tid  = threadIdx.x;
    const int lane = tid & 31, wid = tid >> 5;
    const int mw = wid & 1, nw = wid >> 1;
    const int n0 = blockIdx.y * 128;
    const int k0 = blockIdx.x * 128;

    const __nv_bfloat16* srcs[2];
    srcs[0] = g_a0 + (size_t)n0 * Dd;
    srcs[1] = g_b0 + (size_t)k0 * Dd;

    const uint32_t smbase = smem_u32(sm);

    auto stage_load = [&](int kt, int slot) {
        const int d0 = kt * 64;
        const uint32_t sbase = smbase + slot * STAGE_BYTES;
#pragma unroll
        for (int i = 0; i < 8; i++) {
            int q = i * 256 + tid;
            int tile = q >> 10;
            int qq = q & 1023;
            int r = qq >> 3, c16 = (qq & 7) << 4;
            uint32_t dst = sbase + tile * TILE_BYTES + sw_off(r, c16);
            const void* src = (const char*)(srcs[tile] + (size_t)r * Dd + d0) + c16;
            asm volatile("cp.async.cg.shared.global [%0], [%1], 16;" :: "r"(dst), "l"(src));
        }
        asm volatile("cp.async.commit_group;" ::: "memory");
    };

    float acc[4][4][4];
#pragma unroll
    for (int a = 0; a < 4; a++)
#pragma unroll
        for (int b = 0; b < 4; b++)
#pragma unroll
            for (int c = 0; c < 4; c++) acc[a][b][c] = 0.f;

    stage_load(0, 0);
    stage_load(1, 1);

    for (int kt = 0; kt < 32; kt++) {
        asm volatile("cp.async.wait_group 1;" ::: "memory");
        __syncthreads();
        if (kt + 2 < 32) stage_load(kt + 2, (kt + 2) % 3);

        const uint32_t sb  = smbase + (kt % 3) * STAGE_BYTES;
        const uint32_t a0b = sb;
        const uint32_t b0b = sb + TILE_BYTES;

#pragma unroll
        for (int kk = 0; kk < 4; kk++) {
            const int cba = kk * 32 + ((lane >> 4) & 1) * 16;
            const int cbb = kk * 32 + ((lane >> 3) & 1) * 16;
            uint32_t a0f[4][4];
#pragma unroll
            for (int mi = 0; mi < 4; mi++) {
                int r = mw * 64 + mi * 16 + (lane & 15);
                LDSM4(a0f[mi], a0b + sw_off(r, cba));
            }
            uint32_t b0f[2][4];
#pragma unroll
            for (int nj = 0; nj < 2; nj++) {
                int r = nw * 32 + nj * 16 + (lane & 7) + ((lane >> 4) & 1) * 8;
                LDSM4(b0f[nj], b0b + sw_off(r, cbb));
            }
#pragma unroll
            for (int mi = 0; mi < 4; mi++)
#pragma unroll
                for (int ni = 0; ni < 4; ni++) {
                    const uint32_t* p0 = &b0f[ni >> 1][(ni & 1) * 2];
                    MMA16816(acc[mi][ni], a0f[mi], p0[0], p0[1]);
                }
        }
    }

#pragma unroll
    for (int mi = 0; mi < 4; mi++) {
        int rbase = n0 + mw * 64 + mi * 16 + (lane >> 2);
#pragma unroll
        for (int ni = 0; ni < 4; ni++) {
            int c = k0 + nw * 32 + ni * 8 + (lane & 3) * 2;
            *(float2*)&g_dots[(size_t)rbase * Kk + c]       = make_float2(acc[mi][ni][0], acc[mi][ni][1]);
            *(float2*)&g_dots[(size_t)(rbase + 8) * Kk + c] = make_float2(acc[mi][ni][2], acc[mi][ni][3]);
        }
    }
}

// ---------------------------------------------------------------------------
// fused select: approx argmin + margin shortlist; cnt==1 fast path (validated)
// ---------------------------------------------------------------------------
__global__ void __launch_bounds__(256) k_select(const float* __restrict__ cb) {
    int w = threadIdx.x >> 5, lane = threadIdx.x & 31;
    int n = blockIdx.x * 8 + w;
    float S = g_S[n];
    const float* row = g_dots + (size_t)n * Kk;

    float v[16];
    float best = 3.4e38f;
#pragma unroll
    for (int i = 0; i < 16; i++) {
        int k = i * 32 + lane;
        float m  = __fmul_rn(2.0f, row[k]);
        float v1 = __fadd_rn(S, -m);
        v[i] = __fadd_rn(v1, g_C2[k]);
        best = fminf(best, v[i]);
    }
#pragma unroll
    for (int off = 16; off; off >>= 1)
        best = fminf(best, __shfl_xor_sync(0xFFFFFFFFu, best, off));
    float thr = best + MARGIN;

    unsigned masks[16];
    int total = 0;
#pragma unroll
    for (int i = 0; i < 16; i++) {
        masks[i] = __ballot_sync(0xFFFFFFFFu, v[i] <= thr);
        total += __popc(masks[i]);
    }

    if (total == 1) {
        if (lane == 0) {
            int kk = 0;
#pragma unroll
            for (int i = 0; i < 16; i++)
                if (masks[i]) kk = i * 32 + (__ffs(masks[i]) - 1);
            g_idx[n] = kk;
        }
        return;
    }

    const float* arow = g_at + (size_t)n * Dd;
    unsigned long long bkey = 0xFFFFFFFFFFFFFFFFull;
#pragma unroll
    for (int i = 0; i < 16; i++) {
        unsigned mask = masks[i];
        while (mask) {
            int src = __ffs(mask) - 1;
            mask &= mask - 1;
            int k = i * 32 + src;
            const float* brow = cb + (size_t)k * Dd;
            float acc = 0.f;
#pragma unroll
            for (int j = 0; j < 16; j++) {
                float4 a = *(const float4*)(arow + j * 128 + lane * 4);
                float4 b = *(const float4*)(brow + j * 128 + lane * 4);
                acc = fmaf(a.x, b.x, acc);
                acc = fmaf(a.y, b.y, acc);
                acc = fmaf(a.z, b.z, acc);
                acc = fmaf(a.w, b.w, acc);
            }
#pragma unroll
            for (int off = 16; off; off >>= 1)
                acc += __shfl_xor_sync(0xFFFFFFFFu, acc, off);
            float vv = __fadd_rn(__fadd_rn(S, -__fmul_rn(2.0f, acc)), g_C2[k]);
            unsigned long long kk =
                ((unsigned long long)__float_as_uint(vv) << 32) | (unsigned)k;
            if (kk < bkey) bkey = kk;
        }
    }
    if (lane == 0) g_idx[n] = (int)(bkey & 0xFFFFFFFFull);
}

// ---------------------------------------------------------------------------
// scatter + conv partials: grid (8 t, 4 d-splits, 32 b) = 1024 CTAs.
// Each block: 64 t x 512 d, float2 per lane, double-buffered staging.
// Partials -> g_p1/g_p2 (no atomics, deterministic).
// ---------------------------------------------------------------------------
__global__ void __launch_bounds__(256) k_scatter4(const float* __restrict__ z,
                                                  const float* __restrict__ cb,
                                                  const float* __restrict__ cw,
                                                  float* __restrict__ out) {
    __shared__ int   sidx[64];
    __shared__ float scb[2][64][65];
    __shared__ float r1x[8][33], r1y[8][33], r2x[8][33], r2y[8][33];

    int b     = blockIdx.z;
    int ds    = blockIdx.y;            // d split 0..3
    int t0    = blockIdx.x * 64;
    int dbase = ds * 512;
    int w = threadIdx.x >> 5, lane = threadIdx.x & 31;

    if (threadIdx.x < 64)
        sidx[threadIdx.x] = g_idx[b * Tt + t0 + threadIdx.x];
    __syncthreads();

    // prefetch tile 0: 64 rows x 64 floats
#pragma unroll
    for (int i = 0; i < 4; i++) {
        int q = i * 256 + threadIdx.x;
        int row = q >> 4, c4 = (q & 15) << 2;
        float4 v = *(const float4*)(cb + (size_t)sidx[row] * Dd + dbase + c4);
        scb[0][row][c4 + 0] = v.x;
        scb[0][row][c4 + 1] = v.y;
        scb[0][row][c4 + 2] = v.z;
        scb[0][row][c4 + 3] = v.w;
    }
    __syncthreads();

    float a1x = 0.f, a1y = 0.f, a2x = 0.f, a2y = 0.f;
    for (int dt = 0; dt < 8; dt++) {
        int d0 = dbase + dt * 64;
        int cur = dt & 1;
        if (dt + 1 < 8) {
            int d1 = d0 + 64;
#pragma unroll
            for (int i = 0; i < 4; i++) {
                int q = i * 256 + threadIdx.x;
                int row = q >> 4, c4 = (q & 15) << 2;
                float4 v = *(const float4*)(cb + (size_t)sidx[row] * Dd + d1 + c4);
                scb[cur ^ 1][row][c4 + 0] = v.x;
                scb[cur ^ 1][row][c4 + 1] = v.y;
                scb[cur ^ 1][row][c4 + 2] = v.z;
                scb[cur ^ 1][row][c4 + 3] = v.w;
            }
        }

        const float* zp = z   + (size_t)b * Dd * Tt + (size_t)d0 * Tt + t0 + lane * 2;
        float*       o1 = out + (size_t)b * Dd * Tt + (size_t)d0 * Tt + t0 + lane * 2;
        float*       o3 = o1 + BAR_OFF;
#pragma unroll
        for (int j = 0; j < 8; j++) {
            int dl = w * 8 + j;
            float q0 = scb[cur][lane * 2][dl];
            float q1 = scb[cur][lane * 2 + 1][dl];
            float2 zv = *(const float2*)&zp[(size_t)dl * Tt];
            float zq0 = __fadd_rn(zv.x, __fadd_rn(q0, -zv.x));
            float zq1 = __fadd_rn(zv.y, __fadd_rn(q1, -zv.y));
            *(float2*)&o1[(size_t)dl * Tt] = make_float2(zq0, zq1);
            *(float2*)&o3[(size_t)dl * Tt] = make_float2(q0, q1);
            float wv = __ldg(cw + d0 + dl);
            a1x += zq0 * wv; a1y += zq1 * wv;
            a2x += q0 * wv;  a2y += q1 * wv;
        }
        __syncthreads();
    }

    r1x[w][lane] = a1x; r1y[w][lane] = a1y;
    r2x[w][lane] = a2x; r2y[w][lane] = a2y;
    __syncthreads();
    if (w == 0) {
        float s1x = 0.f, s1y = 0.f, s2x = 0.f, s2y = 0.f;
#pragma unroll
        for (int i = 0; i < 8; i++) {
            s1x += r1x[i][lane]; s1y += r1y[i][lane];
            s2x += r2x[i][lane]; s2y += r2y[i][lane];
        }
        int n0i = b * Tt + t0 + lane * 2;
        g_p1[(size_t)n0i * 4 + ds]       = s1x;
        g_p1[(size_t)(n0i + 1) * 4 + ds] = s1y;
        g_p2[(size_t)n0i * 4 + ds]       = s2x;
        g_p2[(size_t)(n0i + 1) * 4 + ds] = s2y;
    }
}

// ---------------------------------------------------------------------------
// finish: deterministic fixed-order reduction of the 4 conv partials + bias
// ---------------------------------------------------------------------------
__global__ void k_finish(const float* __restrict__ cbias, float* __restrict__ out) {
    int n = blockIdx.x * 256 + threadIdx.x;
    float bias = __ldg(cbias);
    float4 p1 = *(const float4*)&g_p1[(size_t)n * 4];
    float4 p2 = *(const float4*)&g_p2[(size_t)n * 4];
    out[OH1_OFF + n] = bias + (((p1.x + p1.y) + p1.z) + p1.w);
    out[OH2_OFF + n] = bias + (((p2.x + p2.y) + p2.z) + p2.w);
}

// ---------------------------------------------------------------------------
extern "C" void kernel_launch(void* const* d_in, const int* in_sizes, int n_in,
                              void* d_out, int out_size) {
    const float* z      = (const float*)d_in[0];
    const float* cb     = (const float*)d_in[1];
    const float* conv_w = (const float*)d_in[2];
    const float* conv_b = (const float*)d_in[3];
    float* out = (float*)d_out;

    cudaFuncSetAttribute(k_gemm_mma, cudaFuncAttributeMaxDynamicSharedMemorySize, SM_SZ);

    k_prep<<<1024, 256>>>(z, cb);
    k_gemm_mma<<<dim3(Kk / 128, Nn / 128), 256, SM_SZ>>>();
    k_select<<<Nn / 8, 256>>>(cb);
    k_scatter4<<<dim3(Tt / 64, 4, Bb), 256>>>(z, cb, conv_w, out);
    k_finish<<<Nn / 256, 256>>>(conv_b, out);
}

// round 15
// speedup vs baseline: 1.1841x; 1.0711x over previous
#include <cuda_runtime.h>
#include <cuda_bf16.h>
#include <cstdint>

#define Bb 32
#define Dd 2048
#define Tt 512
#define Kk 512
#define Nn (Bb*Tt)            // 16384
#define BDT (Bb*Dd*Tt)        // 33554432
#define OH1_OFF BDT
#define BAR_OFF (BDT + Nn)
#define OH2_OFF (2*BDT + Nn)
#define MARGIN 2e-3f

// ---------------- scratch (device globals; allocation-free) ----------------
__device__ __nv_bfloat16 g_a0[(size_t)Nn * Dd];   // z bf16, n-major
__device__ __nv_bfloat16 g_b0[(size_t)Kk * Dd];   // codebook bf16
__device__ float g_dots[(size_t)Nn * Kk];         // approx scores (32 MB)
__device__ float g_S[Nn];
__device__ float g_C2[Kk];
__device__ int   g_idx[Nn];
__device__ float g_p1[(size_t)Nn * 4];            // conv partials (z_q_x path)
__device__ float g_p2[(size_t)Nn * 4];            // conv partials (quant path)

__device__ __forceinline__ uint32_t smem_u32(const void* p) {
    uint32_t a;
    asm("{ .reg .u64 t; cvta.to.shared.u64 t, %1; cvt.u32.u64 %0, t; }" : "=r"(a) : "l"(p));
    return a;
}
__device__ __forceinline__ uint32_t sw_off(int r, int cbyte) {
    return (uint32_t)(r * 128 + (cbyte ^ ((r & 7) << 4)));
}

#define LDSM4(f, addr) \
    asm volatile("ldmatrix.sync.aligned.m8n8.x4.shared.b16 {%0,%1,%2,%3}, [%4];" \
        : "=r"((f)[0]), "=r"((f)[1]), "=r"((f)[2]), "=r"((f)[3]) : "r"(addr))

#define MMA16816(d, a, br0, br1) \
    asm volatile("mma.sync.aligned.m16n8k16.row.col.f32.bf16.bf16.f32 " \
        "{%0,%1,%2,%3}, {%4,%5,%6,%7}, {%8,%9}, {%0,%1,%2,%3};" \
        : "+f"((d)[0]), "+f"((d)[1]), "+f"((d)[2]), "+f"((d)[3]) \
        : "r"((a)[0]), "r"((a)[1]), "r"((a)[2]), "r"((a)[3]), "r"(br0), "r"(br1))

// ---------------------------------------------------------------------------
// fused prep: blocks [0,512) = codebook C2 + bf16 copy;
//             blocks [512,1024) = z transpose/split + S (no g_at write)
// ---------------------------------------------------------------------------
__global__ void __launch_bounds__(256) k_prep(const float* __restrict__ z,
                                              const float* __restrict__ cb) {
    __shared__ float s[64][33];
    __shared__ float red[32][9];
    __shared__ float smr[256];

    if (blockIdx.x < 512) {
        int k = blockIdx.x;
        const float4* row = (const float4*)(cb + (size_t)k * Dd);
        float sv = 0.f;
        for (int i = threadIdx.x; i < Dd / 4; i += 256) {
            float4 v = row[i];
            sv += v.x * v.x + v.y * v.y + v.z * v.z + v.w * v.w;
            __nv_bfloat16 h[4];
            h[0] = __float2bfloat16(v.x); h[1] = __float2bfloat16(v.y);
            h[2] = __float2bfloat16(v.z); h[3] = __float2bfloat16(v.w);
            *(uint2*)&g_b0[(size_t)k * Dd + 4 * i] = *(uint2*)h;
        }
        smr[threadIdx.x] = sv;
        __syncthreads();
        for (int o = 128; o; o >>= 1) {
            if (threadIdx.x < o) smr[threadIdx.x] += smr[threadIdx.x + o];
            __syncthreads();
        }
        if (threadIdx.x == 0) g_C2[k] = smr[0];
        return;
    }

    int idx = blockIdx.x - 512;
    int t0 = (idx & 15) * 32;
    int b  = idx >> 4;
    const float* zp = z + (size_t)b * Dd * Tt + t0;

    int nl = threadIdx.x >> 3;
    int dc = (threadIdx.x & 7) * 8;
    size_t nrow = (size_t)(b * Tt + t0 + nl) * Dd;
    float Sacc = 0.f;

    for (int dt = 0; dt < 32; dt++) {
        int d0 = dt * 64;
#pragma unroll
        for (int i = 0; i < 8; i++) {
            int e = i * 256 + threadIdx.x;
            int dr = e >> 5, tc = e & 31;
            s[dr][tc] = zp[(size_t)(d0 + dr) * Tt + tc];
        }
        __syncthreads();

        float f[8];
        __nv_bfloat16 h[8];
#pragma unroll
        for (int j = 0; j < 8; j++) {
            f[j] = s[dc + j][nl];
            h[j] = __float2bfloat16(f[j]);
            Sacc += f[j] * f[j];
        }
        *(uint4*)&g_a0[nrow + d0 + dc] = *(uint4*)h;
        __syncthreads();
    }

    red[nl][threadIdx.x & 7] = Sacc;
    __syncthreads();
    if (threadIdx.x < 32) {
        float t = 0.f;
#pragma unroll
        for (int g = 0; g < 8; g++) t += red[threadIdx.x][g];
        g_S[b * Tt + t0 + threadIdx.x] = t;
    }
}

// ---------------------------------------------------------------------------
// single-pass bf16 mma.sync GEMM -> g_dots  (exact R11 kernel, validated)
// ---------------------------------------------------------------------------
#define TILE_BYTES 16384
#define STAGE_BYTES (2*TILE_BYTES)
#define SM_SZ (3*STAGE_BYTES)      // 98304

__global__ void __launch_bounds__(256) k_gemm_mma() {
    extern __shared__ char sm[];
    const int tid  = threadIdx.x;
    const int lane = tid & 31, wid = tid >> 5;
    const int mw = wid & 1, nw = wid >> 1;
    const int n0 = blockIdx.y * 128;
    const int k0 = blockIdx.x * 128;

    const __nv_bfloat16* srcs[2];
    srcs[0] = g_a0 + (size_t)n0 * Dd;
    srcs[1] = g_b0 + (size_t)k0 * Dd;

    const uint32_t smbase = smem_u32(sm);

    auto stage_load = [&](int kt, int slot) {
        const int d0 = kt * 64;
        const uint32_t sbase = smbase + slot * STAGE_BYTES;
#pragma unroll
        for (int i = 0; i < 8; i++) {
            int q = i * 256 + tid;
            int tile = q >> 10;
            int qq = q & 1023;
            int r = qq >> 3, c16 = (qq & 7) << 4;
            uint32_t dst = sbase + tile * TILE_BYTES + sw_off(r, c16);
            const void* src = (const char*)(srcs[tile] + (size_t)r * Dd + d0) + c16;
            asm volatile("cp.async.cg.shared.global [%0], [%1], 16;" :: "r"(dst), "l"(src));
        }
        asm volatile("cp.async.commit_group;" ::: "memory");
    };

    float acc[4][4][4];
#pragma unroll
    for (int a = 0; a < 4; a++)
#pragma unroll
        for (int b = 0; b < 4; b++)
#pragma unroll
            for (int c = 0; c < 4; c++) acc[a][b][c] = 0.f;

    stage_load(0, 0);
    stage_load(1, 1);

    for (int kt = 0; kt < 32; kt++) {
        asm volatile("cp.async.wait_group 1;" ::: "memory");
        __syncthreads();
        if (kt + 2 < 32) stage_load(kt + 2, (kt + 2) % 3);

        const uint32_t sb  = smbase + (kt % 3) * STAGE_BYTES;
        const uint32_t a0b = sb;
        const uint32_t b0b = sb + TILE_BYTES;

#pragma unroll
        for (int kk = 0; kk < 4; kk++) {
            const int cba = kk * 32 + ((lane >> 4) & 1) * 16;
            const int cbb = kk * 32 + ((lane >> 3) & 1) * 16;
            uint32_t a0f[4][4];
#pragma unroll
            for (int mi = 0; mi < 4; mi++) {
                int r = mw * 64 + mi * 16 + (lane & 15);
                LDSM4(a0f[mi], a0b + sw_off(r, cba));
            }
            uint32_t b0f[2][4];
#pragma unroll
            for (int nj = 0; nj < 2; nj++) {
                int r = nw * 32 + nj * 16 + (lane & 7) + ((lane >> 4) & 1) * 8;
                LDSM4(b0f[nj], b0b + sw_off(r, cbb));
            }
#pragma unroll
            for (int mi = 0; mi < 4; mi++)
#pragma unroll
                for (int ni = 0; ni < 4; ni++) {
                    const uint32_t* p0 = &b0f[ni >> 1][(ni & 1) * 2];
                    MMA16816(acc[mi][ni], a0f[mi], p0[0], p0[1]);
                }
        }
    }

#pragma unroll
    for (int mi = 0; mi < 4; mi++) {
        int rbase = n0 + mw * 64 + mi * 16 + (lane >> 2);
#pragma unroll
        for (int ni = 0; ni < 4; ni++) {
            int c = k0 + nw * 32 + ni * 8 + (lane & 3) * 2;
            *(float2*)&g_dots[(size_t)rbase * Kk + c]       = make_float2(acc[mi][ni][0], acc[mi][ni][1]);
            *(float2*)&g_dots[(size_t)(rbase + 8) * Kk + c] = make_float2(acc[mi][ni][2], acc[mi][ni][3]);
        }
    }
}

// ---------------------------------------------------------------------------
// fused select: approx argmin + margin shortlist; cnt==1 fast path (validated)
// exact path reads z directly (strided) — same values, same fmaf order
// ---------------------------------------------------------------------------
__global__ void __launch_bounds__(256) k_select(const float* __restrict__ z,
                                                const float* __restrict__ cb) {
    int w = threadIdx.x >> 5, lane = threadIdx.x & 31;
    int n = blockIdx.x * 8 + w;
    float S = g_S[n];
    const float* row = g_dots + (size_t)n * Kk;

    float v[16];
    float best = 3.4e38f;
#pragma unroll
    for (int i = 0; i < 16; i++) {
        int k = i * 32 + lane;
        float m  = __fmul_rn(2.0f, row[k]);
        float v1 = __fadd_rn(S, -m);
        v[i] = __fadd_rn(v1, g_C2[k]);
        best = fminf(best, v[i]);
    }
#pragma unroll
    for (int off = 16; off; off >>= 1)
        best = fminf(best, __shfl_xor_sync(0xFFFFFFFFu, best, off));
    float thr = best + MARGIN;

    unsigned masks[16];
    int total = 0;
#pragma unroll
    for (int i = 0; i < 16; i++) {
        masks[i] = __ballot_sync(0xFFFFFFFFu, v[i] <= thr);
        total += __popc(masks[i]);
    }

    if (total == 1) {
        if (lane == 0) {
            int kk = 0;
#pragma unroll
            for (int i = 0; i < 16; i++)
                if (masks[i]) kk = i * 32 + (__ffs(masks[i]) - 1);
            g_idx[n] = kk;
        }
        return;
    }

    // exact path: load this row's z values (strided from (B,D,T)) once into regs
    const float* zrow = z + (size_t)(n >> 9) * Dd * Tt + (n & (Tt - 1));
    float4 a[16];
#pragma unroll
    for (int j = 0; j < 16; j++) {
        int d = j * 128 + lane * 4;
        a[j].x = zrow[(size_t)(d + 0) * Tt];
        a[j].y = zrow[(size_t)(d + 1) * Tt];
        a[j].z = zrow[(size_t)(d + 2) * Tt];
        a[j].w = zrow[(size_t)(d + 3) * Tt];
    }

    unsigned long long bkey = 0xFFFFFFFFFFFFFFFFull;
#pragma unroll
    for (int i = 0; i < 16; i++) {
        unsigned mask = masks[i];
        while (mask) {
            int src = __ffs(mask) - 1;
            mask &= mask - 1;
            int k = i * 32 + src;
            const float* brow = cb + (size_t)k * Dd;
            float acc = 0.f;
#pragma unroll
            for (int j = 0; j < 16; j++) {
                float4 b = *(const float4*)(brow + j * 128 + lane * 4);
                acc = fmaf(a[j].x, b.x, acc);
                acc = fmaf(a[j].y, b.y, acc);
                acc = fmaf(a[j].z, b.z, acc);
                acc = fmaf(a[j].w, b.w, acc);
            }
#pragma unroll
            for (int off = 16; off; off >>= 1)
                acc += __shfl_xor_sync(0xFFFFFFFFu, acc, off);
            float vv = __fadd_rn(__fadd_rn(S, -__fmul_rn(2.0f, acc)), g_C2[k]);
            unsigned long long kk =
                ((unsigned long long)__float_as_uint(vv) << 32) | (unsigned)k;
            if (kk < bkey) bkey = kk;
        }
    }
    if (lane == 0) g_idx[n] = (int)(bkey & 0xFFFFFFFFull);
}

// ---------------------------------------------------------------------------
// scatter + conv partials: 1024 CTAs (8t x 4ds x 32b), 64t x 512d each;
// explicit z-load batching (MLP=8) before compute/store pass
// ---------------------------------------------------------------------------
__global__ void __launch_bounds__(256) k_scatter4(const float* __restrict__ z,
                                                  const float* __restrict__ cb,
                                                  const float* __restrict__ cw,
                                                  float* __restrict__ out) {
    __shared__ int   sidx[64];
    __shared__ float scb[2][64][65];
    __shared__ float r1x[8][33], r1y[8][33], r2x[8][33], r2y[8][33];

    int b     = blockIdx.z;
    int ds    = blockIdx.y;
    int t0    = blockIdx.x * 64;
    int dbase = ds * 512;
    int w = threadIdx.x >> 5, lane = threadIdx.x & 31;

    if (threadIdx.x < 64)
        sidx[threadIdx.x] = g_idx[b * Tt + t0 + threadIdx.x];
    __syncthreads();

#pragma unroll
    for (int i = 0; i < 4; i++) {
        int q = i * 256 + threadIdx.x;
        int row = q >> 4, c4 = (q & 15) << 2;
        float4 v = *(const float4*)(cb + (size_t)sidx[row] * Dd + dbase + c4);
        scb[0][row][c4 + 0] = v.x;
        scb[0][row][c4 + 1] = v.y;
        scb[0][row][c4 + 2] = v.z;
        scb[0][row][c4 + 3] = v.w;
    }
    __syncthreads();

    float a1x = 0.f, a1y = 0.f, a2x = 0.f, a2y = 0.f;
    for (int dt = 0; dt < 8; dt++) {
        int d0 = dbase + dt * 64;
        int cur = dt & 1;
        if (dt + 1 < 8) {
            int d1 = d0 + 64;
#pragma unroll
            for (int i = 0; i < 4; i++) {
                int q = i * 256 + threadIdx.x;
                int row = q >> 4, c4 = (q & 15) << 2;
                float4 v = *(const float4*)(cb + (size_t)sidx[row] * Dd + d1 + c4);
                scb[cur ^ 1][row][c4 + 0] = v.x;
                scb[cur ^ 1][row][c4 + 1] = v.y;
                scb[cur ^ 1][row][c4 + 2] = v.z;
                scb[cur ^ 1][row][c4 + 3] = v.w;
            }
        }

        const float* zp = z   + (size_t)b * Dd * Tt + (size_t)d0 * Tt + t0 + lane * 2;
        float*       o1 = out + (size_t)b * Dd * Tt + (size_t)d0 * Tt + t0 + lane * 2;
        float*       o3 = o1 + BAR_OFF;

        // batch all 8 z loads first (MLP=8 per thread)
        float2 zv[8];
#pragma unroll
        for (int j = 0; j < 8; j++)
            zv[j] = *(const float2*)&zp[(size_t)(w * 8 + j) * Tt];

#pragma unroll
        for (int j = 0; j < 8; j++) {
            int dl = w * 8 + j;
            float q0 = scb[cur][lane * 2][dl];
            float q1 = scb[cur][lane * 2 + 1][dl];
            float zq0 = __fadd_rn(zv[j].x, __fadd_rn(q0, -zv[j].x));
            float zq1 = __fadd_rn(zv[j].y, __fadd_rn(q1, -zv[j].y));
            *(float2*)&o1[(size_t)dl * Tt] = make_float2(zq0, zq1);
            *(float2*)&o3[(size_t)dl * Tt] = make_float2(q0, q1);
            float wv = __ldg(cw + d0 + dl);
            a1x += zq0 * wv; a1y += zq1 * wv;
            a2x += q0 * wv;  a2y += q1 * wv;
        }
        __syncthreads();
    }

    r1x[w][lane] = a1x; r1y[w][lane] = a1y;
    r2x[w][lane] = a2x; r2y[w][lane] = a2y;
    __syncthreads();
    if (w == 0) {
        float s1x = 0.f, s1y = 0.f, s2x = 0.f, s2y = 0.f;
#pragma unroll
        for (int i = 0; i < 8; i++) {
            s1x += r1x[i][lane]; s1y += r1y[i][lane];
            s2x += r2x[i][lane]; s2y += r2y[i][lane];
        }
        int n0i = b * Tt + t0 + lane * 2;
        g_p1[(size_t)n0i * 4 + ds]       = s1x;
        g_p1[(size_t)(n0i + 1) * 4 + ds] = s1y;
        g_p2[(size_t)n0i * 4 + ds]       = s2x;
        g_p2[(size_t)(n0i + 1) * 4 + ds] = s2y;
    }
}

// ---------------------------------------------------------------------------
// finish: deterministic fixed-order reduction of the 4 conv partials + bias
// ---------------------------------------------------------------------------
__global__ void k_finish(const float* __restrict__ cbias, float* __restrict__ out) {
    int n = blockIdx.x * 256 + threadIdx.x;
    float bias = __ldg(cbias);
    float4 p1 = *(const float4*)&g_p1[(size_t)n * 4];
    float4 p2 = *(const float4*)&g_p2[(size_t)n * 4];
    out[OH1_OFF + n] = bias + (((p1.x + p1.y) + p1.z) + p1.w);
    out[OH2_OFF + n] = bias + (((p2.x + p2.y) + p2.z) + p2.w);
}

// ---------------------------------------------------------------------------
extern "C" void kernel_launch(void* const* d_in, const int* in_sizes, int n_in,
                              void* d_out, int out_size) {
    const float* z      = (const float*)d_in[0];
    const float* cb     = (const float*)d_in[1];
    const float* conv_w = (const float*)d_in[2];
    const float* conv_b = (const float*)d_in[3];
    float* out = (float*)d_out;

    cudaFuncSetAttribute(k_gemm_mma, cudaFuncAttributeMaxDynamicSharedMemorySize, SM_SZ);

    k_prep<<<1024, 256>>>(z, cb);
    k_gemm_mma<<<dim3(Kk / 128, Nn / 128), 256, SM_SZ>>>();
    k_select<<<Nn / 8, 256>>>(z, cb);
    k_scatter4<<<dim3(Tt / 64, 4, Bb), 256>>>(z, cb, conv_w, out);
    k_finish<<<Nn / 256, 256>>>(conv_b, out);
}

// round 16
// speedup vs baseline: 1.2465x; 1.0527x over previous
#include <cuda_runtime.h>
#include <cuda_bf16.h>
#include <cstdint>

#define Bb 32
#define Dd 2048
#define Tt 512
#define Kk 512
#define Nn (Bb*Tt)            // 16384
#define BDT (Bb*Dd*Tt)        // 33554432
#define OH1_OFF BDT
#define BAR_OFF (BDT + Nn)
#define OH2_OFF (2*BDT + Nn)
#define MARGIN 2e-3f

// ---------------- scratch (device globals; allocation-free) ----------------
__device__ __nv_bfloat16 g_a0[(size_t)Nn * Dd];   // z bf16, n-major
__device__ __nv_bfloat16 g_b0[(size_t)Kk * Dd];   // codebook bf16
__device__ float g_dots[(size_t)Nn * Kk];         // approx scores (32 MB)
__device__ float g_S[Nn];
__device__ float g_C2[Kk];
__device__ int   g_idx[Nn];
__device__ float g_p1[(size_t)Nn * 8];            // conv partials (z_q_x path)
__device__ float g_p2[(size_t)Nn * 8];            // conv partials (quant path)

__device__ __forceinline__ uint32_t smem_u32(const void* p) {
    uint32_t a;
    asm("{ .reg .u64 t; cvta.to.shared.u64 t, %1; cvt.u32.u64 %0, t; }" : "=r"(a) : "l"(p));
    return a;
}
__device__ __forceinline__ uint32_t sw_off(int r, int cbyte) {
    return (uint32_t)(r * 128 + (cbyte ^ ((r & 7) << 4)));
}

#define LDSM4(f, addr) \
    asm volatile("ldmatrix.sync.aligned.m8n8.x4.shared.b16 {%0,%1,%2,%3}, [%4];" \
        : "=r"((f)[0]), "=r"((f)[1]), "=r"((f)[2]), "=r"((f)[3]) : "r"(addr))

#define MMA16816(d, a, br0, br1) \
    asm volatile("mma.sync.aligned.m16n8k16.row.col.f32.bf16.bf16.f32 " \
        "{%0,%1,%2,%3}, {%4,%5,%6,%7}, {%8,%9}, {%0,%1,%2,%3};" \
        : "+f"((d)[0]), "+f"((d)[1]), "+f"((d)[2]), "+f"((d)[3]) \
        : "r"((a)[0]), "r"((a)[1]), "r"((a)[2]), "r"((a)[3]), "r"(br0), "r"(br1))

// ---------------------------------------------------------------------------
// fused prep: blocks [0,512) = codebook C2 + bf16 copy;
//             blocks [512,1024) = z transpose/split + S  (validated R15)
// ---------------------------------------------------------------------------
__global__ void __launch_bounds__(256) k_prep(const float* __restrict__ z,
                                              const float* __restrict__ cb) {
    __shared__ float s[64][33];
    __shared__ float red[32][9];
    __shared__ float smr[256];

    if (blockIdx.x < 512) {
        int k = blockIdx.x;
        const float4* row = (const float4*)(cb + (size_t)k * Dd);
        float sv = 0.f;
        for (int i = threadIdx.x; i < Dd / 4; i += 256) {
            float4 v = row[i];
            sv += v.x * v.x + v.y * v.y + v.z * v.z + v.w * v.w;
            __nv_bfloat16 h[4];
            h[0] = __float2bfloat16(v.x); h[1] = __float2bfloat16(v.y);
            h[2] = __float2bfloat16(v.z); h[3] = __float2bfloat16(v.w);
            *(uint2*)&g_b0[(size_t)k * Dd + 4 * i] = *(uint2*)h;
        }
        smr[threadIdx.x] = sv;
        __syncthreads();
        for (int o = 128; o; o >>= 1) {
            if (threadIdx.x < o) smr[threadIdx.x] += smr[threadIdx.x + o];
            __syncthreads();
        }
        if (threadIdx.x == 0) g_C2[k] = smr[0];
        return;
    }

    int idx = blockIdx.x - 512;
    int t0 = (idx & 15) * 32;
    int b  = idx >> 4;
    const float* zp = z + (size_t)b * Dd * Tt + t0;

    int nl = threadIdx.x >> 3;
    int dc = (threadIdx.x & 7) * 8;
    size_t nrow = (size_t)(b * Tt + t0 + nl) * Dd;
    float Sacc = 0.f;

    for (int dt = 0; dt < 32; dt++) {
        int d0 = dt * 64;
#pragma unroll
        for (int i = 0; i < 8; i++) {
            int e = i * 256 + threadIdx.x;
            int dr = e >> 5, tc = e & 31;
            s[dr][tc] = zp[(size_t)(d0 + dr) * Tt + tc];
        }
        __syncthreads();

        float f[8];
        __nv_bfloat16 h[8];
#pragma unroll
        for (int j = 0; j < 8; j++) {
            f[j] = s[dc + j][nl];
            h[j] = __float2bfloat16(f[j]);
            Sacc += f[j] * f[j];
        }
        *(uint4*)&g_a0[nrow + d0 + dc] = *(uint4*)h;
        __syncthreads();
    }

    red[nl][threadIdx.x & 7] = Sacc;
    __syncthreads();
    if (threadIdx.x < 32) {
        float t = 0.f;
#pragma unroll
        for (int g = 0; g < 8; g++) t += red[threadIdx.x][g];
        g_S[b * Tt + t0 + threadIdx.x] = t;
    }
}

// ---------------------------------------------------------------------------
// single-pass bf16 mma.sync GEMM -> g_dots  (exact R11 kernel, validated)
// ---------------------------------------------------------------------------
#define TILE_BYTES 16384
#define STAGE_BYTES (2*TILE_BYTES)
#define SM_SZ (3*STAGE_BYTES)      // 98304

__global__ void __launch_bounds__(256) k_gemm_mma() {
    extern __shared__ char sm[];
    const int tid  = threadIdx.x;
    const int lane = tid & 31, wid = tid >> 5;
    const int mw = wid & 1, nw = wid >> 1;
    const int n0 = blockIdx.y * 128;
    const int k0 = blockIdx.x * 128;

    const __nv_bfloat16* srcs[2];
    srcs[0] = g_a0 + (size_t)n0 * Dd;
    srcs[1] = g_b0 + (size_t)k0 * Dd;

    const uint32_t smbase = smem_u32(sm);

    auto stage_load = [&](int kt, int slot) {
        const int d0 = kt * 64;
        const uint32_t sbase = smbase + slot * STAGE_BYTES;
#pragma unroll
        for (int i = 0; i < 8; i++) {
            int q = i * 256 + tid;
            int tile = q >> 10;
            int qq = q & 1023;
            int r = qq >> 3, c16 = (qq & 7) << 4;
            uint32_t dst = sbase + tile * TILE_BYTES + sw_off(r, c16);
            const void* src = (const char*)(srcs[tile] + (size_t)r * Dd + d0) + c16;
            asm volatile("cp.async.cg.shared.global [%0], [%1], 16;" :: "r"(dst), "l"(src));
        }
        asm volatile("cp.async.commit_group;" ::: "memory");
    };

    float acc[4][4][4];
#pragma unroll
    for (int a = 0; a < 4; a++)
#pragma unroll
        for (int b = 0; b < 4; b++)
#pragma unroll
            for (int c = 0; c < 4; c++) acc[a][b][c] = 0.f;

    stage_load(0, 0);
    stage_load(1, 1);

    for (int kt = 0; kt < 32; kt++) {
        asm volatile("cp.async.wait_group 1;" ::: "memory");
        __syncthreads();
        if (kt + 2 < 32) stage_load(kt + 2, (kt + 2) % 3);

        const uint32_t sb  = smbase + (kt % 3) * STAGE_BYTES;
        const uint32_t a0b = sb;
        const uint32_t b0b = sb + TILE_BYTES;

#pragma unroll
        for (int kk = 0; kk < 4; kk++) {
            const int cba = kk * 32 + ((lane >> 4) & 1) * 16;
            const int cbb = kk * 32 + ((lane >> 3) & 1) * 16;
            uint32_t a0f[4][4];
#pragma unroll
            for (int mi = 0; mi < 4; mi++) {
                int r = mw * 64 + mi * 16 + (lane & 15);
                LDSM4(a0f[mi], a0b + sw_off(r, cba));
            }
            uint32_t b0f[2][4];
#pragma unroll
            for (int nj = 0; nj < 2; nj++) {
                int r = nw * 32 + nj * 16 + (lane & 7) + ((lane >> 4) & 1) * 8;
                LDSM4(b0f[nj], b0b + sw_off(r, cbb));
            }
#pragma unroll
            for (int mi = 0; mi < 4; mi++)
#pragma unroll
                for (int ni = 0; ni < 4; ni++) {
                    const uint32_t* p0 = &b0f[ni >> 1][(ni & 1) * 2];
                    MMA16816(acc[mi][ni], a0f[mi], p0[0], p0[1]);
                }
        }
    }

#pragma unroll
    for (int mi = 0; mi < 4; mi++) {
        int rbase = n0 + mw * 64 + mi * 16 + (lane >> 2);
#pragma unroll
        for (int ni = 0; ni < 4; ni++) {
            int c = k0 + nw * 32 + ni * 8 + (lane & 3) * 2;
            *(float2*)&g_dots[(size_t)rbase * Kk + c]       = make_float2(acc[mi][ni][0], acc[mi][ni][1]);
            *(float2*)&g_dots[(size_t)(rbase + 8) * Kk + c] = make_float2(acc[mi][ni][2], acc[mi][ni][3]);
        }
    }
}

// ---------------------------------------------------------------------------
// fused select: float4 dots reads (k = lane*16 + i layout), C2 staged in smem,
// cnt==1 fast path; exact path reads z directly. Order-independent logic, so
// the k-relayout preserves indices exactly.
// ---------------------------------------------------------------------------
__global__ void __launch_bounds__(256) k_select(const float* __restrict__ z,
                                                const float* __restrict__ cb) {
    __shared__ float sC2[512];
    int w = threadIdx.x >> 5, lane = threadIdx.x & 31;
    int n = blockIdx.x * 8 + w;

    sC2[threadIdx.x]       = g_C2[threadIdx.x];
    sC2[threadIdx.x + 256] = g_C2[threadIdx.x + 256];
    __syncthreads();

    float S = g_S[n];
    const float* row = g_dots + (size_t)n * Kk;

    // lane owns k in [lane*16, lane*16+16)
    float v[16];
    float best = 3.4e38f;
#pragma unroll
    for (int q = 0; q < 4; q++) {
        float4 d4 = *(const float4*)&row[lane * 16 + q * 4];
        int kb = lane * 16 + q * 4;
        v[q*4+0] = __fadd_rn(__fadd_rn(S, -__fmul_rn(2.0f, d4.x)), sC2[kb + 0]);
        v[q*4+1] = __fadd_rn(__fadd_rn(S, -__fmul_rn(2.0f, d4.y)), sC2[kb + 1]);
        v[q*4+2] = __fadd_rn(__fadd_rn(S, -__fmul_rn(2.0f, d4.z)), sC2[kb + 2]);
        v[q*4+3] = __fadd_rn(__fadd_rn(S, -__fmul_rn(2.0f, d4.w)), sC2[kb + 3]);
    }
#pragma unroll
    for (int i = 0; i < 16; i++) best = fminf(best, v[i]);
#pragma unroll
    for (int off = 16; off; off >>= 1)
        best = fminf(best, __shfl_xor_sync(0xFFFFFFFFu, best, off));
    float thr = best + MARGIN;

    unsigned masks[16];
    int total = 0;
#pragma unroll
    for (int i = 0; i < 16; i++) {
        masks[i] = __ballot_sync(0xFFFFFFFFu, v[i] <= thr);
        total += __popc(masks[i]);
    }

    if (total == 1) {
        if (lane == 0) {
            int kk = 0;
#pragma unroll
            for (int i = 0; i < 16; i++)
                if (masks[i]) kk = (__ffs(masks[i]) - 1) * 16 + i;
            g_idx[n] = kk;
        }
        return;
    }

    // exact path: load this row's z values (strided from (B,D,T)) once
    const float* zrow = z + (size_t)(n >> 9) * Dd * Tt + (n & (Tt - 1));
    float4 a[16];
#pragma unroll
    for (int j = 0; j < 16; j++) {
        int d = j * 128 + lane * 4;
        a[j].x = zrow[(size_t)(d + 0) * Tt];
        a[j].y = zrow[(size_t)(d + 1) * Tt];
        a[j].z = zrow[(size_t)(d + 2) * Tt];
        a[j].w = zrow[(size_t)(d + 3) * Tt];
    }

    unsigned long long bkey = 0xFFFFFFFFFFFFFFFFull;
#pragma unroll
    for (int i = 0; i < 16; i++) {
        unsigned mask = masks[i];
        while (mask) {
            int src = __ffs(mask) - 1;
            mask &= mask - 1;
            int k = src * 16 + i;
            const float* brow = cb + (size_t)k * Dd;
            float acc = 0.f;
#pragma unroll
            for (int j = 0; j < 16; j++) {
                float4 b = *(const float4*)(brow + j * 128 + lane * 4);
                acc = fmaf(a[j].x, b.x, acc);
                acc = fmaf(a[j].y, b.y, acc);
                acc = fmaf(a[j].z, b.z, acc);
                acc = fmaf(a[j].w, b.w, acc);
            }
#pragma unroll
            for (int off = 16; off; off >>= 1)
                acc += __shfl_xor_sync(0xFFFFFFFFu, acc, off);
            float vv = __fadd_rn(__fadd_rn(S, -__fmul_rn(2.0f, acc)), sC2[k]);
            unsigned long long kk =
                ((unsigned long long)__float_as_uint(vv) << 32) | (unsigned)k;
            if (kk < bkey) bkey = kk;
        }
    }
    if (lane == 0) g_idx[n] = (int)(bkey & 0xFFFFFFFFull);
}

// ---------------------------------------------------------------------------
// scatter + conv partials: 2048 CTAs (8t x 8ds x 32b), 64t x 256d each;
// explicit z-load batching (MLP=8)
// ---------------------------------------------------------------------------
__global__ void __launch_bounds__(256) k_scatter4(const float* __restrict__ z,
                                                  const float* __restrict__ cb,
                                                  const float* __restrict__ cw,
                                                  float* __restrict__ out) {
    __shared__ int   sidx[64];
    __shared__ float scb[2][64][65];
    __shared__ float r1x[8][33], r1y[8][33], r2x[8][33], r2y[8][33];

    int b     = blockIdx.z;
    int ds    = blockIdx.y;            // 0..7
    int t0    = blockIdx.x * 64;
    int dbase = ds * 256;
    int w = threadIdx.x >> 5, lane = threadIdx.x & 31;

    if (threadIdx.x < 64)
        sidx[threadIdx.x] = g_idx[b * Tt + t0 + threadIdx.x];
    __syncthreads();

#pragma unroll
    for (int i = 0; i < 4; i++) {
        int q = i * 256 + threadIdx.x;
        int row = q >> 4, c4 = (q & 15) << 2;
        float4 v = *(const float4*)(cb + (size_t)sidx[row] * Dd + dbase + c4);
        scb[0][row][c4 + 0] = v.x;
        scb[0][row][c4 + 1] = v.y;
        scb[0][row][c4 + 2] = v.z;
        scb[0][row][c4 + 3] = v.w;
    }
    __syncthreads();

    float a1x = 0.f, a1y = 0.f, a2x = 0.f, a2y = 0.f;
    for (int dt = 0; dt < 4; dt++) {
        int d0 = dbase + dt * 64;
        int cur = dt & 1;
        if (dt + 1 < 4) {
            int d1 = d0 + 64;
#pragma unroll
            for (int i = 0; i < 4; i++) {
                int q = i * 256 + threadIdx.x;
                int row = q >> 4, c4 = (q & 15) << 2;
                float4 v = *(const float4*)(cb + (size_t)sidx[row] * Dd + d1 + c4);
                scb[cur ^ 1][row][c4 + 0] = v.x;
                scb[cur ^ 1][row][c4 + 1] = v.y;
                scb[cur ^ 1][row][c4 + 2] = v.z;
                scb[cur ^ 1][row][c4 + 3] = v.w;
            }
        }

        const float* zp = z   + (size_t)b * Dd * Tt + (size_t)d0 * Tt + t0 + lane * 2;
        float*       o1 = out + (size_t)b * Dd * Tt + (size_t)d0 * Tt + t0 + lane * 2;
        float*       o3 = o1 + BAR_OFF;

        float2 zv[8];
#pragma unroll
        for (int j = 0; j < 8; j++)
            zv[j] = *(const float2*)&zp[(size_t)(w * 8 + j) * Tt];

#pragma unroll
        for (int j = 0; j < 8; j++) {
            int dl = w * 8 + j;
            float q0 = scb[cur][lane * 2][dl];
            float q1 = scb[cur][lane * 2 + 1][dl];
            float zq0 = __fadd_rn(zv[j].x, __fadd_rn(q0, -zv[j].x));
            float zq1 = __fadd_rn(zv[j].y, __fadd_rn(q1, -zv[j].y));
            *(float2*)&o1[(size_t)dl * Tt] = make_float2(zq0, zq1);
            *(float2*)&o3[(size_t)dl * Tt] = make_float2(q0, q1);
            float wv = __ldg(cw + d0 + dl);
            a1x += zq0 * wv; a1y += zq1 * wv;
            a2x += q0 * wv;  a2y += q1 * wv;
        }
        __syncthreads();
    }

    r1x[w][lane] = a1x; r1y[w][lane] = a1y;
    r2x[w][lane] = a2x; r2y[w][lane] = a2y;
    __syncthreads();
    if (w == 0) {
        float s1x = 0.f, s1y = 0.f, s2x = 0.f, s2y = 0.f;
#pragma unroll
        for (int i = 0; i < 8; i++) {
            s1x += r1x[i][lane]; s1y += r1y[i][lane];
            s2x += r2x[i][lane]; s2y += r2y[i][lane];
        }
        int n0i = b * Tt + t0 + lane * 2;
        g_p1[(size_t)n0i * 8 + ds]       = s1x;
        g_p1[(size_t)(n0i + 1) * 8 + ds] = s1y;
        g_p2[(size_t)n0i * 8 + ds]       = s2x;
        g_p2[(size_t)(n0i + 1) * 8 + ds] = s2y;
    }
}

// ---------------------------------------------------------------------------
// finish: deterministic fixed-order reduction of the 8 conv partials + bias
// ---------------------------------------------------------------------------
__global__ void k_finish(const float* __restrict__ cbias, float* __restrict__ out) {
    int n = blockIdx.x * 256 + threadIdx.x;
    float bias = __ldg(cbias);
    float4 p1a = *(const float4*)&g_p1[(size_t)n * 8];
    float4 p1b = *(const float4*)&g_p1[(size_t)n * 8 + 4];
    float4 p2a = *(const float4*)&g_p2[(size_t)n * 8];
    float4 p2b = *(const float4*)&g_p2[(size_t)n * 8 + 4];
    float s1 = ((((((p1a.x + p1a.y) + p1a.z) + p1a.w) + p1b.x) + p1b.y) + p1b.z) + p1b.w;
    float s2 = ((((((p2a.x + p2a.y) + p2a.z) + p2a.w) + p2b.x) + p2b.y) + p2b.z) + p2b.w;
    out[OH1_OFF + n] = bias + s1;
    out[OH2_OFF + n] = bias + s2;
}

// ---------------------------------------------------------------------------
extern "C" void kernel_launch(void* const* d_in, const int* in_sizes, int n_in,
                              void* d_out, int out_size) {
    const float* z      = (const float*)d_in[0];
    const float* cb     = (const float*)d_in[1];
    const float* conv_w = (const float*)d_in[2];
    const float* conv_b = (const float*)d_in[3];
    float* out = (float*)d_out;

    cudaFuncSetAttribute(k_gemm_mma, cudaFuncAttributeMaxDynamicSharedMemorySize, SM_SZ);

    k_prep<<<1024, 256>>>(z, cb);
    k_gemm_mma<<<dim3(Kk / 128, Nn / 128), 256, SM_SZ>>>();
    k_select<<<Nn / 8, 256>>>(z, cb);
    k_scatter4<<<dim3(Tt / 64, 8, Bb), 256>>>(z, cb, conv_w, out);
    k_finish<<<Nn / 256, 256>>>(conv_b, out);
}

// round 17
// speedup vs baseline: 1.2758x; 1.0235x over previous
#include <cuda_runtime.h>
#include <cuda_bf16.h>
#include <cstdint>

#define Bb 32
#define Dd 2048
#define Tt 512
#define Kk 512
#define Nn (Bb*Tt)            // 16384
#define BDT (Bb*Dd*Tt)        // 33554432
#define OH1_OFF BDT
#define BAR_OFF (BDT + Nn)
#define OH2_OFF (2*BDT + Nn)
#define MARGIN 2e-3f

// ---------------- scratch (device globals; allocation-free) ----------------
__device__ __nv_bfloat16 g_a0[(size_t)Nn * Dd];   // z bf16, n-major
__device__ __nv_bfloat16 g_b0[(size_t)Kk * Dd];   // codebook bf16
__device__ float g_dots[(size_t)Nn * Kk];         // approx scores (32 MB)
__device__ float g_S[Nn];
__device__ float g_C2[Kk];
__device__ int   g_idx[Nn];
__device__ float g_p1[(size_t)Nn * 8];            // conv partials (z_q_x path)
__device__ float g_p2[(size_t)Nn * 8];            // conv partials (quant path)

__device__ __forceinline__ uint32_t smem_u32(const void* p) {
    uint32_t a;
    asm("{ .reg .u64 t; cvta.to.shared.u64 t, %1; cvt.u32.u64 %0, t; }" : "=r"(a) : "l"(p));
    return a;
}
__device__ __forceinline__ uint32_t sw_off(int r, int cbyte) {
    return (uint32_t)(r * 128 + (cbyte ^ ((r & 7) << 4)));
}

#define LDSM4(f, addr) \
    asm volatile("ldmatrix.sync.aligned.m8n8.x4.shared.b16 {%0,%1,%2,%3}, [%4];" \
        : "=r"((f)[0]), "=r"((f)[1]), "=r"((f)[2]), "=r"((f)[3]) : "r"(addr))

#define MMA16816(d, a, br0, br1) \
    asm volatile("mma.sync.aligned.m16n8k16.row.col.f32.bf16.bf16.f32 " \
        "{%0,%1,%2,%3}, {%4,%5,%6,%7}, {%8,%9}, {%0,%1,%2,%3};" \
        : "+f"((d)[0]), "+f"((d)[1]), "+f"((d)[2]), "+f"((d)[3]) \
        : "r"((a)[0]), "r"((a)[1]), "r"((a)[2]), "r"((a)[3]), "r"(br0), "r"(br1))

// ---------------------------------------------------------------------------
// fused prep: blocks [0,512) = codebook C2 + bf16 copy;
//             blocks [512,1024) = z transpose/split + S  (validated R15/R16)
// ---------------------------------------------------------------------------
__global__ void __launch_bounds__(256) k_prep(const float* __restrict__ z,
                                              const float* __restrict__ cb) {
    __shared__ float s[64][33];
    __shared__ float red[32][9];
    __shared__ float smr[256];

    if (blockIdx.x < 512) {
        int k = blockIdx.x;
        const float4* row = (const float4*)(cb + (size_t)k * Dd);
        float sv = 0.f;
        for (int i = threadIdx.x; i < Dd / 4; i += 256) {
            float4 v = row[i];
            sv += v.x * v.x + v.y * v.y + v.z * v.z + v.w * v.w;
            __nv_bfloat16 h[4];
            h[0] = __float2bfloat16(v.x); h[1] = __float2bfloat16(v.y);
            h[2] = __float2bfloat16(v.z); h[3] = __float2bfloat16(v.w);
            *(uint2*)&g_b0[(size_t)k * Dd + 4 * i] = *(uint2*)h;
        }
        smr[threadIdx.x] = sv;
        __syncthreads();
        for (int o = 128; o; o >>= 1) {
            if (threadIdx.x < o) smr[threadIdx.x] += smr[threadIdx.x + o];
            __syncthreads();
        }
        if (threadIdx.x == 0) g_C2[k] = smr[0];
        return;
    }

    int idx = blockIdx.x - 512;
    int t0 = (idx & 15) * 32;
    int b  = idx >> 4;
    const float* zp = z + (size_t)b * Dd * Tt + t0;

    int nl = threadIdx.x >> 3;
    int dc = (threadIdx.x & 7) * 8;
    size_t nrow = (size_t)(b * Tt + t0 + nl) * Dd;
    float Sacc = 0.f;

    for (int dt = 0; dt < 32; dt++) {
        int d0 = dt * 64;
#pragma unroll
        for (int i = 0; i < 8; i++) {
            int e = i * 256 + threadIdx.x;
            int dr = e >> 5, tc = e & 31;
            s[dr][tc] = zp[(size_t)(d0 + dr) * Tt + tc];
        }
        __syncthreads();

        float f[8];
        __nv_bfloat16 h[8];
#pragma unroll
        for (int j = 0; j < 8; j++) {
            f[j] = s[dc + j][nl];
            h[j] = __float2bfloat16(f[j]);
            Sacc += f[j] * f[j];
        }
        *(uint4*)&g_a0[nrow + d0 + dc] = *(uint4*)h;
        __syncthreads();
    }

    red[nl][threadIdx.x & 7] = Sacc;
    __syncthreads();
    if (threadIdx.x < 32) {
        float t = 0.f;
#pragma unroll
        for (int g = 0; g < 8; g++) t += red[threadIdx.x][g];
        g_S[b * Tt + t0 + threadIdx.x] = t;
    }
}

// ---------------------------------------------------------------------------
// single-pass bf16 mma.sync GEMM -> g_dots  (exact R11 kernel, validated)
// ---------------------------------------------------------------------------
#define TILE_BYTES 16384
#define STAGE_BYTES (2*TILE_BYTES)
#define SM_SZ (3*STAGE_BYTES)      // 98304

__global__ void __launch_bounds__(256) k_gemm_mma() {
    extern __shared__ char sm[];
    const int tid  = threadIdx.x;
    const int lane = tid & 31, wid = tid >> 5;
    const int mw = wid & 1, nw = wid >> 1;
    const int n0 = blockIdx.y * 128;
    const int k0 = blockIdx.x * 128;

    const __nv_bfloat16* srcs[2];
    srcs[0] = g_a0 + (size_t)n0 * Dd;
    srcs[1] = g_b0 + (size_t)k0 * Dd;

    const uint32_t smbase = smem_u32(sm);

    auto stage_load = [&](int kt, int slot) {
        const int d0 = kt * 64;
        const uint32_t sbase = smbase + slot * STAGE_BYTES;
#pragma unroll
        for (int i = 0; i < 8; i++) {
            int q = i * 256 + tid;
            int tile = q >> 10;
            int qq = q & 1023;
            int r = qq >> 3, c16 = (qq & 7) << 4;
            uint32_t dst = sbase + tile * TILE_BYTES + sw_off(r, c16);
            const void* src = (const char*)(srcs[tile] + (size_t)r * Dd + d0) + c16;
            asm volatile("cp.async.cg.shared.global [%0], [%1], 16;" :: "r"(dst), "l"(src));
        }
        asm volatile("cp.async.commit_group;" ::: "memory");
    };

    float acc[4][4][4];
#pragma unroll
    for (int a = 0; a < 4; a++)
#pragma unroll
        for (int b = 0; b < 4; b++)
#pragma unroll
            for (int c = 0; c < 4; c++) acc[a][b][c] = 0.f;

    stage_load(0, 0);
    stage_load(1, 1);

    for (int kt = 0; kt < 32; kt++) {
        asm volatile("cp.async.wait_group 1;" ::: "memory");
        __syncthreads();
        if (kt + 2 < 32) stage_load(kt + 2, (kt + 2) % 3);

        const uint32_t sb  = smbase + (kt % 3) * STAGE_BYTES;
        const uint32_t a0b = sb;
        const uint32_t b0b = sb + TILE_BYTES;

#pragma unroll
        for (int kk = 0; kk < 4; kk++) {
            const int cba = kk * 32 + ((lane >> 4) & 1) * 16;
            const int cbb = kk * 32 + ((lane >> 3) & 1) * 16;
            uint32_t a0f[4][4];
#pragma unroll
            for (int mi = 0; mi < 4; mi++) {
                int r = mw * 64 + mi * 16 + (lane & 15);
                LDSM4(a0f[mi], a0b + sw_off(r, cba));
            }
            uint32_t b0f[2][4];
#pragma unroll
            for (int nj = 0; nj < 2; nj++) {
                int r = nw * 32 + nj * 16 + (lane & 7) + ((lane >> 4) & 1) * 8;
                LDSM4(b0f[nj], b0b + sw_off(r, cbb));
            }
#pragma unroll
            for (int mi = 0; mi < 4; mi++)
#pragma unroll
                for (int ni = 0; ni < 4; ni++) {
                    const uint32_t* p0 = &b0f[ni >> 1][(ni & 1) * 2];
                    MMA16816(acc[mi][ni], a0f[mi], p0[0], p0[1]);
                }
        }
    }

#pragma unroll
    for (int mi = 0; mi < 4; mi++) {
        int rbase = n0 + mw * 64 + mi * 16 + (lane >> 2);
#pragma unroll
        for (int ni = 0; ni < 4; ni++) {
            int c = k0 + nw * 32 + ni * 8 + (lane & 3) * 2;
            *(float2*)&g_dots[(size_t)rbase * Kk + c]       = make_float2(acc[mi][ni][0], acc[mi][ni][1]);
            *(float2*)&g_dots[(size_t)(rbase + 8) * Kk + c] = make_float2(acc[mi][ni][2], acc[mi][ni][3]);
        }
    }
}

// ---------------------------------------------------------------------------
// fused select: float4 dots reads (k = lane*16 + i layout), C2 staged in smem,
// cnt==1 fast path; exact path reads z directly  (validated R16)
// ---------------------------------------------------------------------------
__global__ void __launch_bounds__(256) k_select(const float* __restrict__ z,
                                                const float* __restrict__ cb) {
    __shared__ float sC2[512];
    int w = threadIdx.x >> 5, lane = threadIdx.x & 31;
    int n = blockIdx.x * 8 + w;

    sC2[threadIdx.x]       = g_C2[threadIdx.x];
    sC2[threadIdx.x + 256] = g_C2[threadIdx.x + 256];
    __syncthreads();

    float S = g_S[n];
    const float* row = g_dots + (size_t)n * Kk;

    float v[16];
    float best = 3.4e38f;
#pragma unroll
    for (int q = 0; q < 4; q++) {
        float4 d4 = *(const float4*)&row[lane * 16 + q * 4];
        int kb = lane * 16 + q * 4;
        v[q*4+0] = __fadd_rn(__fadd_rn(S, -__fmul_rn(2.0f, d4.x)), sC2[kb + 0]);
        v[q*4+1] = __fadd_rn(__fadd_rn(S, -__fmul_rn(2.0f, d4.y)), sC2[kb + 1]);
        v[q*4+2] = __fadd_rn(__fadd_rn(S, -__fmul_rn(2.0f, d4.z)), sC2[kb + 2]);
        v[q*4+3] = __fadd_rn(__fadd_rn(S, -__fmul_rn(2.0f, d4.w)), sC2[kb + 3]);
    }
#pragma unroll
    for (int i = 0; i < 16; i++) best = fminf(best, v[i]);
#pragma unroll
    for (int off = 16; off; off >>= 1)
        best = fminf(best, __shfl_xor_sync(0xFFFFFFFFu, best, off));
    float thr = best + MARGIN;

    unsigned masks[16];
    int total = 0;
#pragma unroll
    for (int i = 0; i < 16; i++) {
        masks[i] = __ballot_sync(0xFFFFFFFFu, v[i] <= thr);
        total += __popc(masks[i]);
    }

    if (total == 1) {
        if (lane == 0) {
            int kk = 0;
#pragma unroll
            for (int i = 0; i < 16; i++)
                if (masks[i]) kk = (__ffs(masks[i]) - 1) * 16 + i;
            g_idx[n] = kk;
        }
        return;
    }

    const float* zrow = z + (size_t)(n >> 9) * Dd * Tt + (n & (Tt - 1));
    float4 a[16];
#pragma unroll
    for (int j = 0; j < 16; j++) {
        int d = j * 128 + lane * 4;
        a[j].x = zrow[(size_t)(d + 0) * Tt];
        a[j].y = zrow[(size_t)(d + 1) * Tt];
        a[j].z = zrow[(size_t)(d + 2) * Tt];
        a[j].w = zrow[(size_t)(d + 3) * Tt];
    }

    unsigned long long bkey = 0xFFFFFFFFFFFFFFFFull;
#pragma unroll
    for (int i = 0; i < 16; i++) {
        unsigned mask = masks[i];
        while (mask) {
            int src = __ffs(mask) - 1;
            mask &= mask - 1;
            int k = src * 16 + i;
            const float* brow = cb + (size_t)k * Dd;
            float acc = 0.f;
#pragma unroll
            for (int j = 0; j < 16; j++) {
                float4 b = *(const float4*)(brow + j * 128 + lane * 4);
                acc = fmaf(a[j].x, b.x, acc);
                acc = fmaf(a[j].y, b.y, acc);
                acc = fmaf(a[j].z, b.z, acc);
                acc = fmaf(a[j].w, b.w, acc);
            }
#pragma unroll
            for (int off = 16; off; off >>= 1)
                acc += __shfl_xor_sync(0xFFFFFFFFu, acc, off);
            float vv = __fadd_rn(__fadd_rn(S, -__fmul_rn(2.0f, acc)), sC2[k]);
            unsigned long long kk =
                ((unsigned long long)__float_as_uint(vv) << 32) | (unsigned)k;
            if (kk < bkey) bkey = kk;
        }
    }
    if (lane == 0) g_idx[n] = (int)(bkey & 0xFFFFFFFFull);
}

// ---------------------------------------------------------------------------
// scatter + conv partials: 2048 CTAs (8t x 8ds x 32b), 64t x 256d each;
// SINGLE-buffered staging (16.6 KB) -> 8 CTAs/SM; z-load batching (MLP=8)
// ---------------------------------------------------------------------------
__global__ void __launch_bounds__(256) k_scatter5(const float* __restrict__ z,
                                                  const float* __restrict__ cb,
                                                  const float* __restrict__ cw,
                                                  float* __restrict__ out) {
    __shared__ int   sidx[64];
    __shared__ float scb[64][65];
    __shared__ float r1x[8][33], r1y[8][33], r2x[8][33], r2y[8][33];

    int b     = blockIdx.z;
    int ds    = blockIdx.y;            // 0..7
    int t0    = blockIdx.x * 64;
    int dbase = ds * 256;
    int w = threadIdx.x >> 5, lane = threadIdx.x & 31;

    if (threadIdx.x < 64)
        sidx[threadIdx.x] = g_idx[b * Tt + t0 + threadIdx.x];
    __syncthreads();

    float a1x = 0.f, a1y = 0.f, a2x = 0.f, a2y = 0.f;
    for (int dt = 0; dt < 4; dt++) {
        int d0 = dbase + dt * 64;

        // stage tile: 64 rows x 64 floats
#pragma unroll
        for (int i = 0; i < 4; i++) {
            int q = i * 256 + threadIdx.x;
            int row = q >> 4, c4 = (q & 15) << 2;
            float4 v = *(const float4*)(cb + (size_t)sidx[row] * Dd + d0 + c4);
            scb[row][c4 + 0] = v.x;
            scb[row][c4 + 1] = v.y;
            scb[row][c4 + 2] = v.z;
            scb[row][c4 + 3] = v.w;
        }
        __syncthreads();

        const float* zp = z   + (size_t)b * Dd * Tt + (size_t)d0 * Tt + t0 + lane * 2;
        float*       o1 = out + (size_t)b * Dd * Tt + (size_t)d0 * Tt + t0 + lane * 2;
        float*       o3 = o1 + BAR_OFF;

        float2 zv[8];
#pragma unroll
        for (int j = 0; j < 8; j++)
            zv[j] = *(const float2*)&zp[(size_t)(w * 8 + j) * Tt];

#pragma unroll
        for (int j = 0; j < 8; j++) {
            int dl = w * 8 + j;
            float q0 = scb[lane * 2][dl];
            float q1 = scb[lane * 2 + 1][dl];
            float zq0 = __fadd_rn(zv[j].x, __fadd_rn(q0, -zv[j].x));
            float zq1 = __fadd_rn(zv[j].y, __fadd_rn(q1, -zv[j].y));
            *(float2*)&o1[(size_t)dl * Tt] = make_float2(zq0, zq1);
            *(float2*)&o3[(size_t)dl * Tt] = make_float2(q0, q1);
            float wv = __ldg(cw + d0 + dl);
            a1x += zq0 * wv; a1y += zq1 * wv;
            a2x += q0 * wv;  a2y += q1 * wv;
        }
        __syncthreads();
    }

    r1x[w][lane] = a1x; r1y[w][lane] = a1y;
    r2x[w][lane] = a2x; r2y[w][lane] = a2y;
    __syncthreads();
    if (w == 0) {
        float s1x = 0.f, s1y = 0.f, s2x = 0.f, s2y = 0.f;
#pragma unroll
        for (int i = 0; i < 8; i++) {
            s1x += r1x[i][lane]; s1y += r1y[i][lane];
            s2x += r2x[i][lane]; s2y += r2y[i][lane];
        }
        int n0i = b * Tt + t0 + lane * 2;
        g_p1[(size_t)n0i * 8 + ds]       = s1x;
        g_p1[(size_t)(n0i + 1) * 8 + ds] = s1y;
        g_p2[(size_t)n0i * 8 + ds]       = s2x;
        g_p2[(size_t)(n0i + 1) * 8 + ds] = s2y;
    }
}

// ---------------------------------------------------------------------------
// finish: deterministic fixed-order reduction of the 8 conv partials + bias
// ---------------------------------------------------------------------------
__global__ void k_finish(const float* __restrict__ cbias, float* __restrict__ out) {
    int n = blockIdx.x * 256 + threadIdx.x;
    float bias = __ldg(cbias);
    float4 p1a = *(const float4*)&g_p1[(size_t)n * 8];
    float4 p1b = *(const float4*)&g_p1[(size_t)n * 8 + 4];
    float4 p2a = *(const float4*)&g_p2[(size_t)n * 8];
    float4 p2b = *(const float4*)&g_p2[(size_t)n * 8 + 4];
    float s1 = ((((((p1a.x + p1a.y) + p1a.z) + p1a.w) + p1b.x) + p1b.y) + p1b.z) + p1b.w;
    float s2 = ((((((p2a.x + p2a.y) + p2a.z) + p2a.w) + p2b.x) + p2b.y) + p2b.z) + p2b.w;
    out[OH1_OFF + n] = bias + s1;
    out[OH2_OFF + n] = bias + s2;
}

// ---------------------------------------------------------------------------
extern "C" void kernel_launch(void* const* d_in, const int* in_sizes, int n_in,
                              void* d_out, int out_size) {
    const float* z      = (const float*)d_in[0];
    const float* cb     = (const float*)d_in[1];
    const float* conv_w = (const float*)d_in[2];
    const float* conv_b = (const float*)d_in[3];
    float* out = (float*)d_out;

    cudaFuncSetAttribute(k_gemm_mma, cudaFuncAttributeMaxDynamicSharedMemorySize, SM_SZ);

    k_prep<<<1024, 256>>>(z, cb);
    k_gemm_mma<<<dim3(Kk / 128, Nn / 128), 256, SM_SZ>>>();
    k_select<<<Nn / 8, 256>>>(z, cb);
    k_scatter5<<<dim3(Tt / 64, 8, Bb), 256>>>(z, cb, conv_w, out);
    k_finish<<<Nn / 256, 256>>>(conv_b, out);
}